// round 11
// baseline (speedup 1.0000x reference)
#include <cuda_runtime.h>
#include <math.h>
#include <stdint.h>

static constexpr int kN  = 384;
static constexpr int kD  = 256;
static constexpr int kH  = 8;
static constexpr float kScale = 0.17677669529663687f;  // 1/sqrt(32)

// ---------------- scratch (__device__ globals; no allocation) ----------------
__device__ __align__(16) float qx_g[kN * kD];
__device__ __align__(16) float kx_g[kN * kD];
__device__ __align__(16) float vx_g[kN * kD];
__device__ __align__(16) float cen_g[kN * kH];          // qx . bk_e
__device__ __align__(16) float cne_g[kN * kH];          // kx . bq_e
__device__ __align__(16) float u_g[kN * kH * kD];       // [i][h][d]
__device__ __align__(16) float w_g[kN * kH * kD];       // [n][h][d]
__device__ __align__(16) float PT_g[kN * kD * 12];      // [n][d*12+h], 4 pad (0)
__device__ __align__(16) float g_part_g[3 * kN * kH * kD];
__device__ __align__(16) float sum_part_g[6 * kN * kH]; // [(ch*2+jq)][i][h]

__device__ __forceinline__ void cpa16(void* smem, const void* gmem)
{
    unsigned s = (unsigned)__cvta_generic_to_shared(smem);
    asm volatile("cp.async.ca.shared.global [%0], [%1], 16;\n" :: "r"(s), "l"(gmem));
}
#define CP_COMMIT() asm volatile("cp.async.commit_group;\n" ::: "memory")
#define CP_WAIT2()  asm volatile("cp.async.wait_group 2;\n" ::: "memory")

// ---------------- K1: qx/kx/vx projections + score constants ----------------
__global__ __launch_bounds__(256) void k1_proj(
    const float* __restrict__ x,
    const float* __restrict__ Wq, const float* __restrict__ bq,
    const float* __restrict__ Wk, const float* __restrict__ bk,
    const float* __restrict__ Wv, const float* __restrict__ bv,
    const float* __restrict__ bk_e, const float* __restrict__ bq_e)
{
    __shared__ float xs[kD];
    int i = blockIdx.x, c = threadIdx.x;
    xs[c] = x[i * kD + c];
    __syncthreads();
    int h = c >> 5, k = c & 31;
    const float* wq = Wq + h * 8192 + k;
    const float* wk = Wk + h * 8192 + k;
    const float* wv = Wv + h * 8192 + k;
    float q = 0.f, kk = 0.f, v = 0.f;
#pragma unroll 8
    for (int d = 0; d < kD; d++) {
        float xv = xs[d];
        q  = fmaf(xv, wq[d * 32], q);
        kk = fmaf(xv, wk[d * 32], kk);
        v  = fmaf(xv, wv[d * 32], v);
    }
    q += bq[c]; kk += bk[c]; v += bv[c];
    qx_g[i * kD + c] = q;
    kx_g[i * kD + c] = kk;
    vx_g[i * kD + c] = v;

    float ce = bk_e[c] * q;
    float cn = bq_e[c] * kk;
#pragma unroll
    for (int o = 16; o; o >>= 1) {
        ce += __shfl_xor_sync(0xffffffffu, ce, o);
        cn += __shfl_xor_sync(0xffffffffu, cn, o);
    }
    if (k == 0) { cen_g[i * kH + h] = ce; cne_g[i * kH + h] = cn; }
}

// ---------------- K1b: u / w / PT tables -------------------------------------
__global__ __launch_bounds__(256) void k1b_uwp(
    const float* __restrict__ Wk_e,
    const float* __restrict__ Wq_e,
    const float* __restrict__ WOe)
{
    __shared__ float qs[16 * 32], ks[16 * 32], vs[16 * 32];
    int ib = blockIdx.x, h = blockIdx.y;
    int d = threadIdx.x;
    for (int idx = threadIdx.x; idx < 512; idx += 256) {
        int ii = idx >> 5, k = idx & 31;
        int g = (ib * 16 + ii) * kD + h * 32 + k;
        qs[idx] = qx_g[g]; ks[idx] = kx_g[g]; vs[idx] = vx_g[g];
    }
    __syncthreads();

    float wr[32];
#pragma unroll
    for (int k = 0; k < 32; k++) wr[k] = Wk_e[h * 8192 + d * 32 + k];
    for (int ii = 0; ii < 16; ii++) {
        float a = 0.f;
#pragma unroll
        for (int k = 0; k < 32; k++) a = fmaf(wr[k], qs[ii * 32 + k], a);
        u_g[((ib * 16 + ii) * kH + h) * kD + d] = a;
    }
#pragma unroll
    for (int k = 0; k < 32; k++) wr[k] = Wq_e[h * 8192 + d * 32 + k];
    for (int ii = 0; ii < 16; ii++) {
        float a = 0.f;
#pragma unroll
        for (int k = 0; k < 32; k++) a = fmaf(wr[k], ks[ii * 32 + k], a);
        w_g[((ib * 16 + ii) * kH + h) * kD + d] = a;
    }
#pragma unroll
    for (int k = 0; k < 32; k++) wr[k] = WOe[(h * 32 + k) * kD + d];
    for (int ii = 0; ii < 16; ii++) {
        float a = 0.f;
#pragma unroll
        for (int k = 0; k < 32; k++) a = fmaf(wr[k], vs[ii * 32 + k], a);
        PT_g[(size_t)(ib * 16 + ii) * 3072 + d * 12 + h] = a;   // pads stay 0
    }
}

// ---------------- K_fused: pipelined scores/softmax/g/e_out ------------------
// 4 i-rows, 2 j per slot, 4-slot ring, 1 barrier/iter, 512 thr.
// Slot (float4): E 512 | W 1024 | PT 1536 (stride-12) | cne 4 = 3076 f4.
static constexpr int STG_F4 = 3076;
static constexpr int FUSED_SMEM = 4 * STG_F4 * 16;   // 196864 B

__device__ __forceinline__ void kf_prefetch(float4* st, const float* e, int i0, int j0)
{
    int t = threadIdx.x;
#pragma unroll
    for (int k = 0; k < 7; k++) {
        int idx = t + k * 512;
        if (idx >= STG_F4) break;
        if (idx < 512) {
            int jq = idx >> 8, r = idx & 255;
            int ii = r >> 6, c = r & 63;
            cpa16(st + idx,
                  (const float4*)(e) + ((size_t)(i0 + ii) * kN + (j0 + jq)) * 64 + c);
        } else if (idx < 1536) {
            int r = idx - 512;
            int jq = r >> 9, q = r & 511;
            cpa16(st + idx, (const float4*)w_g + (size_t)(j0 + jq) * 512 + q);
        } else if (idx < 3072) {
            int r = idx - 1536;
            int jq = (r >= 768) ? 1 : 0;
            int q  = r - jq * 768;
            cpa16(st + idx, (const float4*)PT_g + (size_t)(j0 + jq) * 768 + q);
        } else {
            cpa16(st + idx, (const float4*)cne_g + (size_t)j0 * 2 + (idx - 3072));
        }
    }
}

__global__ __launch_bounds__(512, 1) void k_fused(
    const float* __restrict__ e, const float* __restrict__ bOe,
    float* __restrict__ e_out)
{
    extern __shared__ float4 smem4[];
    __shared__ __align__(16) float  p_s[2][2][4][8];   // [buf][jq][ii][h]
    __shared__ __align__(16) float2 a_s[2][2][4][8];   // [buf][jq][ii][h] = (ai,aj)
    __shared__ float cen_s[32], cnei_s[32];

    int t = threadIdx.x;
    int i0 = blockIdx.x * 4;
    int ch = blockIdx.y;
    int jbase = ch * 128;

    // score mapping: 64 (jq,ii,h) groups x 8-lane dot segments
    int seg = t & 7, pp = t >> 3;
    int jq_s = pp >> 5, ii_s = (pp >> 3) & 3, h_s = pp & 7;
    // out mapping: 256 d x 2 halves (rows r0,r1)
    int d = t & 255, half = t >> 8;
    int r0 = half * 2, r1 = r0 + 1;

    if (t < 32) { cen_s[t] = cen_g[i0 * 8 + t]; cnei_s[t] = cne_g[i0 * 8 + t]; }

    // loop-invariant regs: u/wi dot segments (8 f4 each), Pi rows, bias
    float4 u_r[8], wi_r[8];
    {
        const float4* ub = (const float4*)u_g + ((size_t)(i0 + ii_s) * 8 + h_s) * 64;
        const float4* wb = (const float4*)w_g + ((size_t)(i0 + ii_s) * 8 + h_s) * 64;
#pragma unroll
        for (int k = 0; k < 8; k++) { u_r[k] = ub[seg + 8 * k]; wi_r[k] = wb[seg + 8 * k]; }
    }
    float Pi0[8], Pi1[8];
#pragma unroll
    for (int h = 0; h < 8; h++) {
        Pi0[h] = PT_g[(size_t)(i0 + r0) * 3072 + d * 12 + h];
        Pi1[h] = PT_g[(size_t)(i0 + r1) * 3072 + d * 12 + h];
    }
    float bo = bOe[d];
    float g_r[16];
#pragma unroll
    for (int q = 0; q < 16; q++) g_r[q] = 0.f;
    float run_sum = 0.f;

    kf_prefetch(smem4,          e, i0, jbase);     CP_COMMIT();
    kf_prefetch(smem4 + STG_F4, e, i0, jbase + 2); CP_COMMIT();

    for (int it = 0; it <= 64; it++) {
        __syncthreads();
        if (it + 2 < 64)
            kf_prefetch(smem4 + (size_t)((it + 2) & 3) * STG_F4, e, i0, jbase + (it + 2) * 2);
        CP_COMMIT();

        if (it > 0) {
            // ---- g + out phase on slot it-1 ----
            const float* stf = (const float*)(smem4 + (size_t)((it - 1) & 3) * STG_F4);
            const float4* pt4 = (const float4*)(stf + 6144);
            int bprev = (it - 1) & 1;
            int j0 = jbase + (it - 1) * 2;
#pragma unroll
            for (int jq = 0; jq < 2; jq++) {
                float4 pjA = pt4[jq * 768 + d * 3];
                float4 pjB = pt4[jq * 768 + d * 3 + 1];
                float pjf[8] = { pjA.x, pjA.y, pjA.z, pjA.w, pjB.x, pjB.y, pjB.z, pjB.w };
#pragma unroll
                for (int ii = 0; ii < 4; ii++) {
                    float ed = stf[jq * 1024 + ii * 256 + d];
                    float4 pv = *(const float4*)&p_s[bprev][jq][ii][half * 4];
                    g_r[ii * 4 + 0] = fmaf(pv.x, ed, g_r[ii * 4 + 0]);
                    g_r[ii * 4 + 1] = fmaf(pv.y, ed, g_r[ii * 4 + 1]);
                    g_r[ii * 4 + 2] = fmaf(pv.z, ed, g_r[ii * 4 + 2]);
                    g_r[ii * 4 + 3] = fmaf(pv.w, ed, g_r[ii * 4 + 3]);
                }
                float o0 = bo, o1 = bo;
                const float4* a0v = (const float4*)&a_s[bprev][jq][r0][0];
                const float4* a1v = (const float4*)&a_s[bprev][jq][r1][0];
#pragma unroll
                for (int q = 0; q < 4; q++) {
                    float4 a0q = a0v[q], a1q = a1v[q];
                    float pje = pjf[2 * q], pjo = pjf[2 * q + 1];
                    o0 = fmaf(a0q.x, Pi0[2 * q],     fmaf(a0q.y, pje, o0));
                    o0 = fmaf(a0q.z, Pi0[2 * q + 1], fmaf(a0q.w, pjo, o0));
                    o1 = fmaf(a1q.x, Pi1[2 * q],     fmaf(a1q.y, pje, o1));
                    o1 = fmaf(a1q.z, Pi1[2 * q + 1], fmaf(a1q.w, pjo, o1));
                }
                int j = j0 + jq;
                e_out[((size_t)(i0 + r0) * kN + j) * kD + d] = o0;
                e_out[((size_t)(i0 + r1) * kN + j) * kD + d] = o1;
            }
        }

        CP_WAIT2();        // slot it&3 ready (hidden behind out phase)

        if (it < 64) {
            // ---- score phase on slot it (8-lane dot groups) ----
            const float4* st4 = smem4 + (size_t)(it & 3) * STG_F4;
            const float* stfl = (const float*)st4;
            int buf = it & 1;
            float acc0 = 0.f, acc1 = 0.f, acc2 = 0.f;
#pragma unroll
            for (int k = 0; k < 8; k++) {
                float4 ev = st4[jq_s * 256 + ii_s * 64 + seg + 8 * k];
                float4 wj = st4[512 + jq_s * 512 + h_s * 64 + seg + 8 * k];
                float4 uu = u_r[k], wi = wi_r[k];
                acc0 = fmaf(ev.x, uu.x, acc0); acc0 = fmaf(ev.y, uu.y, acc0);
                acc0 = fmaf(ev.z, uu.z, acc0); acc0 = fmaf(ev.w, uu.w, acc0);
                acc1 = fmaf(ev.x, wi.x, acc1); acc1 = fmaf(ev.y, wi.y, acc1);
                acc1 = fmaf(ev.z, wi.z, acc1); acc1 = fmaf(ev.w, wi.w, acc1);
                acc2 = fmaf(ev.x, wj.x, acc2); acc2 = fmaf(ev.y, wj.y, acc2);
                acc2 = fmaf(ev.z, wj.z, acc2); acc2 = fmaf(ev.w, wj.w, acc2);
            }
#pragma unroll
            for (int o = 1; o < 8; o <<= 1) {
                acc0 += __shfl_xor_sync(0xffffffffu, acc0, o);
                acc1 += __shfl_xor_sync(0xffffffffu, acc1, o);
                acc2 += __shfl_xor_sync(0xffffffffu, acc2, o);
            }

            if (seg == 0) {
                float pe = __expf((acc0 + cen_s[ii_s * 8 + h_s]) * kScale);
                run_sum += pe;
                p_s[buf][jq_s][ii_s][h_s] = pe;
                float si = (acc1 + cnei_s[ii_s * 8 + h_s]) * kScale;
                float sj = (acc2 + stfl[12288 + jq_s * 8 + h_s]) * kScale;
                float ei = __expf(si), ej = __expf(sj);
                float inv = 1.f / (ei + ej);
                a_s[buf][jq_s][ii_s][h_s] = make_float2(ei * inv, ej * inv);
            }
        }
    }

#pragma unroll
    for (int ii = 0; ii < 4; ii++)
#pragma unroll
        for (int hh = 0; hh < 4; hh++)
            g_part_g[(((size_t)ch * kN + i0 + ii) * 8 + half * 4 + hh) * 256 + d] =
                g_r[ii * 4 + hh];
    if (seg == 0)
        sum_part_g[((size_t)(ch * 2 + jq_s) * kN + i0 + ii_s) * 8 + h_s] = run_sum;
}

// ---------------- K3: reduce + x_out, split-d for parallelism ----------------
__global__ __launch_bounds__(512) void k3_xout(
    const float* __restrict__ Wv_e, const float* __restrict__ bv_e,
    const float* __restrict__ WOx,  const float* __restrict__ bOx,
    float* __restrict__ x_out)
{
    __shared__ float gs[2048];
    __shared__ float xc[256];
    __shared__ float part[512];
    __shared__ float inv_s[8];
    int i = blockIdx.x, t = threadIdx.x;
    int c = t & 255, pr = t >> 8;

    if (t < 8) {
        float s = 0.f;
#pragma unroll
        for (int cch = 0; cch < 6; cch++)
            s += sum_part_g[((size_t)cch * kN + i) * 8 + t];
        inv_s[t] = 1.f / s;
    }
    __syncthreads();
#pragma unroll
    for (int r = 0; r < 4; r++) {
        int idx = t + r * 512;
        int h = idx >> 8;
        float a = g_part_g[((size_t)i * 8 + h) * 256 + (idx & 255)]
                + g_part_g[(((size_t)kN + i) * 8 + h) * 256 + (idx & 255)]
                + g_part_g[(((size_t)2 * kN + i) * 8 + h) * 256 + (idx & 255)];
        gs[idx] = a * inv_s[h];
    }
    __syncthreads();

    // GEMV1: xc[c] = gs[h,:] . Wv_e[h,:,k], split over d halves
    {
        int h = c >> 5, k = c & 31;
        const float* wv = Wv_e + h * 8192 + k;
        const float* gh = gs + h * 256;
        float a0 = 0.f, a1 = 0.f;
        int dbeg = pr * 128;
#pragma unroll 4
        for (int dd = dbeg; dd < dbeg + 128; dd += 2) {
            a0 = fmaf(gh[dd],     wv[dd * 32],       a0);
            a1 = fmaf(gh[dd + 1], wv[(dd + 1) * 32], a1);
        }
        part[t] = a0 + a1;
    }
    __syncthreads();
    if (t < 256) xc[t] = part[t] + part[t + 256] + bv_e[t];
    __syncthreads();

    // GEMV2: x_out[c] = xc . WOx[:,c], split over cc halves
    {
        float o0 = 0.f, o1 = 0.f;
        int cbeg = pr * 128;
#pragma unroll 4
        for (int cc = cbeg; cc < cbeg + 128; cc += 2) {
            o0 = fmaf(xc[cc],     WOx[cc * kD + c],       o0);
            o1 = fmaf(xc[cc + 1], WOx[(cc + 1) * kD + c], o1);
        }
        part[t] = o0 + o1;
    }
    __syncthreads();
    if (t < 256) x_out[(size_t)i * kD + t] = part[t] + part[t + 256] + bOx[t];
}

// ---------------- launch -----------------------------------------------------
extern "C" void kernel_launch(void* const* d_in, const int* in_sizes, int n_in,
                              void* d_out, int out_size)
{
    (void)in_sizes; (void)n_in; (void)out_size;
    const float* x    = (const float*)d_in[0];
    const float* e    = (const float*)d_in[1];
    const float* Wq_x = (const float*)d_in[2];
    const float* bq_x = (const float*)d_in[3];
    const float* Wk_e = (const float*)d_in[4];
    const float* bk_e = (const float*)d_in[5];
    const float* Wv_e = (const float*)d_in[6];
    const float* bv_e = (const float*)d_in[7];
    const float* Wq_e = (const float*)d_in[8];
    const float* bq_e = (const float*)d_in[9];
    const float* Wk_x = (const float*)d_in[10];
    const float* bk_x = (const float*)d_in[11];
    const float* Wv_x = (const float*)d_in[12];
    const float* bv_x = (const float*)d_in[13];
    const float* WOx  = (const float*)d_in[14];
    const float* bOx  = (const float*)d_in[15];
    const float* WOe  = (const float*)d_in[16];
    const float* bOe  = (const float*)d_in[17];

    float* out   = (float*)d_out;
    float* x_out = out;                 // [384,256]
    float* e_out = out + kN * kD;       // [384,384,256]

    cudaFuncSetAttribute(k_fused, cudaFuncAttributeMaxDynamicSharedMemorySize, FUSED_SMEM);

    k1_proj<<<kN, 256>>>(x, Wq_x, bq_x, Wk_x, bk_x, Wv_x, bv_x, bk_e, bq_e);
    k1b_uwp<<<dim3(24, 8), 256>>>(Wk_e, Wq_e, WOe);
    k_fused<<<dim3(96, 3), 512, FUSED_SMEM>>>(e, bOe, e_out);
    k3_xout<<<kN, 512>>>(Wv_e, bv_e, WOx, bOx, x_out);
}

// round 13
// speedup vs baseline: 1.0571x; 1.0571x over previous
#include <cuda_runtime.h>
#include <math.h>
#include <stdint.h>

static constexpr int kN  = 384;
static constexpr int kD  = 256;
static constexpr int kH  = 8;
static constexpr float kScale = 0.17677669529663687f;  // 1/sqrt(32)

// ---------------- scratch (__device__ globals; no allocation) ----------------
__device__ __align__(16) float qx_g[kN * kD];
__device__ __align__(16) float kx_g[kN * kD];
__device__ __align__(16) float vx_g[kN * kD];
__device__ __align__(16) float cen_g[kN * kH];          // qx . bk_e
__device__ __align__(16) float cne_g[kN * kH];          // kx . bq_e
__device__ __align__(16) float u_g[kN * kH * kD];       // [i][h][d]
__device__ __align__(16) float w_g[kN * kH * kD];       // [n][h][d]
__device__ __align__(16) float PT_g[kN * kD * 9];       // [n][d*9+h] stride-9 pad
__device__ __align__(16) float g_part_g[3 * kN * kH * kD];
__device__ __align__(16) float sum_part_g[3 * kN * kH];

__device__ __forceinline__ void cpa16(void* smem, const void* gmem)
{
    unsigned s = (unsigned)__cvta_generic_to_shared(smem);
    asm volatile("cp.async.ca.shared.global [%0], [%1], 16;\n" :: "r"(s), "l"(gmem));
}
#define CP_COMMIT() asm volatile("cp.async.commit_group;\n" ::: "memory")
#define CP_WAIT2()  asm volatile("cp.async.wait_group 2;\n" ::: "memory")

// ---------------- K1: qx/kx/vx projections + score constants ----------------
__global__ __launch_bounds__(256) void k1_proj(
    const float* __restrict__ x,
    const float* __restrict__ Wq, const float* __restrict__ bq,
    const float* __restrict__ Wk, const float* __restrict__ bk,
    const float* __restrict__ Wv, const float* __restrict__ bv,
    const float* __restrict__ bk_e, const float* __restrict__ bq_e)
{
    __shared__ float xs[kD];
    int i = blockIdx.x, c = threadIdx.x;
    xs[c] = x[i * kD + c];
    __syncthreads();
    int h = c >> 5, k = c & 31;
    const float* wq = Wq + h * 8192 + k;
    const float* wk = Wk + h * 8192 + k;
    const float* wv = Wv + h * 8192 + k;
    float q = 0.f, kk = 0.f, v = 0.f;
#pragma unroll 8
    for (int d = 0; d < kD; d++) {
        float xv = xs[d];
        q  = fmaf(xv, wq[d * 32], q);
        kk = fmaf(xv, wk[d * 32], kk);
        v  = fmaf(xv, wv[d * 32], v);
    }
    q += bq[c]; kk += bk[c]; v += bv[c];
    qx_g[i * kD + c] = q;
    kx_g[i * kD + c] = kk;
    vx_g[i * kD + c] = v;

    float ce = bk_e[c] * q;
    float cn = bq_e[c] * kk;
#pragma unroll
    for (int o = 16; o; o >>= 1) {
        ce += __shfl_xor_sync(0xffffffffu, ce, o);
        cn += __shfl_xor_sync(0xffffffffu, cn, o);
    }
    if (k == 0) { cen_g[i * kH + h] = ce; cne_g[i * kH + h] = cn; }
}

// ---------------- K1b: u / w / PT tables -------------------------------------
__global__ __launch_bounds__(256) void k1b_uwp(
    const float* __restrict__ Wk_e,
    const float* __restrict__ Wq_e,
    const float* __restrict__ WOe)
{
    __shared__ float qs[16 * 32], ks[16 * 32], vs[16 * 32];
    int ib = blockIdx.x, h = blockIdx.y;
    int d = threadIdx.x;
    for (int idx = threadIdx.x; idx < 512; idx += 256) {
        int ii = idx >> 5, k = idx & 31;
        int g = (ib * 16 + ii) * kD + h * 32 + k;
        qs[idx] = qx_g[g]; ks[idx] = kx_g[g]; vs[idx] = vx_g[g];
    }
    __syncthreads();

    float wr[32];
#pragma unroll
    for (int k = 0; k < 32; k++) wr[k] = Wk_e[h * 8192 + d * 32 + k];
    for (int ii = 0; ii < 16; ii++) {
        float a = 0.f;
#pragma unroll
        for (int k = 0; k < 32; k++) a = fmaf(wr[k], qs[ii * 32 + k], a);
        u_g[((ib * 16 + ii) * kH + h) * kD + d] = a;
    }
#pragma unroll
    for (int k = 0; k < 32; k++) wr[k] = Wq_e[h * 8192 + d * 32 + k];
    for (int ii = 0; ii < 16; ii++) {
        float a = 0.f;
#pragma unroll
        for (int k = 0; k < 32; k++) a = fmaf(wr[k], ks[ii * 32 + k], a);
        w_g[((ib * 16 + ii) * kH + h) * kD + d] = a;
    }
#pragma unroll
    for (int k = 0; k < 32; k++) wr[k] = WOe[(h * 32 + k) * kD + d];
    for (int ii = 0; ii < 16; ii++) {
        float a = 0.f;
#pragma unroll
        for (int k = 0; k < 32; k++) a = fmaf(wr[k], vs[ii * 32 + k], a);
        PT_g[(size_t)(ib * 16 + ii) * 2304 + d * 9 + h] = a;
    }
}

// ---------------- K_fused: pipelined scores/softmax/g/e_out ------------------
// EXACT R6 configuration (best measured: 364.7us).
// 4 i-rows, 2 j per slot, 4-slot cp.async ring, 1 barrier/iter, 512 thr.
// Slot (float4): E 512 | W 1024 | PT 1152 | cne 4  = 2692 f4 = 43072 B.
static constexpr int STG_F4 = 2692;
static constexpr int FUSED_SMEM = 4 * STG_F4 * 16;   // 172288 B

__device__ __forceinline__ void kf_prefetch(float4* st, const float* e, int i0, int j0)
{
    int t = threadIdx.x;
#pragma unroll
    for (int k = 0; k < 6; k++) {
        int idx = t + k * 512;
        if (idx >= STG_F4) break;
        if (idx < 512) {
            int jq = idx >> 8, r = idx & 255;
            int ii = r >> 6, c = r & 63;
            cpa16(st + idx,
                  (const float4*)(e) + ((size_t)(i0 + ii) * kN + (j0 + jq)) * 64 + c);
        } else if (idx < 1536) {
            int r = idx - 512;
            int jq = r >> 9, q = r & 511;
            cpa16(st + idx, (const float4*)w_g + (size_t)(j0 + jq) * 512 + q);
        } else if (idx < 2688) {
            int r = idx - 1536;
            int jq = (r >= 576) ? 1 : 0;
            int q  = r - jq * 576;
            cpa16(st + idx, (const float4*)PT_g + (size_t)(j0 + jq) * 576 + q);
        } else {
            cpa16(st + idx, (const float4*)cne_g + (size_t)j0 * 2 + (idx - 2688));
        }
    }
}

__global__ __launch_bounds__(512, 1) void k_fused(
    const float* __restrict__ e, const float* __restrict__ bOe,
    float* __restrict__ e_out)
{
    extern __shared__ float4 smem4[];
    __shared__ float  p_s[2][2][32];
    __shared__ float2 a_s[2][2][32];
    __shared__ float  cen_s[32], cnei_s[32];

    int t = threadIdx.x;
    int i0 = blockIdx.x * 4;
    int ch = blockIdx.y;
    int jbase = ch * 128;

    int p = t >> 4, seg = t & 15;       // score: 32 (ii,h) pairs x 16 segs
    int ii_s = p >> 3, h_s = p & 7;
    int d = t & 255, half = t >> 8;     // g/out mapping
    int r0 = half * 2, r1 = half * 2 + 1;

    if (t < 32) { cen_s[t] = cen_g[i0 * 8 + t]; cnei_s[t] = cne_g[i0 * 8 + t]; }

    float4 u_r[4], wi_r[4];
    {
        const float4* ub = (const float4*)u_g + ((size_t)(i0 + ii_s) * 8 + h_s) * 64;
        const float4* wb = (const float4*)w_g + ((size_t)(i0 + ii_s) * 8 + h_s) * 64;
#pragma unroll
        for (int k = 0; k < 4; k++) { u_r[k] = ub[seg + 16 * k]; wi_r[k] = wb[seg + 16 * k]; }
    }
    float Pi0[8], Pi1[8];
#pragma unroll
    for (int h = 0; h < 8; h++) {
        Pi0[h] = PT_g[(size_t)(i0 + r0) * 2304 + d * 9 + h];
        Pi1[h] = PT_g[(size_t)(i0 + r1) * 2304 + d * 9 + h];
    }
    float bo = bOe[d];
    float g_r[16];
#pragma unroll
    for (int q = 0; q < 16; q++) g_r[q] = 0.f;
    float run_sum = 0.f;

    kf_prefetch(smem4,          e, i0, jbase);     CP_COMMIT();
    kf_prefetch(smem4 + STG_F4, e, i0, jbase + 2); CP_COMMIT();

    for (int it = 0; it <= 64; it++) {
        __syncthreads();   // separates score[it-1] p/a writes from out[it] reads,
                           // and all reads of slot (it+2)&3 from its overwrite
        if (it + 2 < 64)
            kf_prefetch(smem4 + (size_t)((it + 2) & 3) * STG_F4, e, i0, jbase + (it + 2) * 2);
        CP_COMMIT();
        CP_WAIT2();        // slot it&3 data ready

        if (it < 64) {
            // ---- score phase on slot it ----
            const float4* st4 = smem4 + (size_t)(it & 3) * STG_F4;
            int buf = it & 1;
            float acc[6];
#pragma unroll
            for (int q = 0; q < 6; q++) acc[q] = 0.f;
#pragma unroll
            for (int k = 0; k < 4; k++) {
                float4 uu = u_r[k], wi = wi_r[k];
#pragma unroll
                for (int jq = 0; jq < 2; jq++) {
                    float4 ev = st4[jq * 256 + ii_s * 64 + seg + 16 * k];
                    float4 wj = st4[512 + jq * 512 + h_s * 64 + seg + 16 * k];
                    float* a = acc + jq * 3;
                    a[0] = fmaf(ev.x, uu.x, a[0]); a[0] = fmaf(ev.y, uu.y, a[0]);
                    a[0] = fmaf(ev.z, uu.z, a[0]); a[0] = fmaf(ev.w, uu.w, a[0]);
                    a[1] = fmaf(ev.x, wi.x, a[1]); a[1] = fmaf(ev.y, wi.y, a[1]);
                    a[1] = fmaf(ev.z, wi.z, a[1]); a[1] = fmaf(ev.w, wi.w, a[1]);
                    a[2] = fmaf(ev.x, wj.x, a[2]); a[2] = fmaf(ev.y, wj.y, a[2]);
                    a[2] = fmaf(ev.z, wj.z, a[2]); a[2] = fmaf(ev.w, wj.w, a[2]);
                }
            }
#pragma unroll
            for (int o = 1; o < 16; o <<= 1)
#pragma unroll
                for (int q = 0; q < 6; q++)
                    acc[q] += __shfl_xor_sync(0xffffffffu, acc[q], o);

            if ((seg & 7) == 0) {          // seg 0 -> jq 0, seg 8 -> jq 1
                int jq = seg >> 3;
                float pe = __expf((acc[jq * 3] + cen_s[p]) * kScale);
                run_sum += pe;
                p_s[buf][jq][p] = pe;
                float si = (acc[jq * 3 + 1] + cnei_s[p]) * kScale;
                float sj = (acc[jq * 3 + 2] + ((const float*)st4)[10752 + jq * 8 + h_s]) * kScale;
                float ei = __expf(si), ej = __expf(sj);
                float inv = 1.f / (ei + ej);
                a_s[buf][jq][p] = make_float2(ei * inv, ej * inv);
            }
        }

        if (it > 0) {
            // ---- g + out phase on slot it-1 ----
            const float* stf = (const float*)(smem4 + (size_t)((it - 1) & 3) * STG_F4);
            const float* ptf = stf + 6144;
            int bprev = (it - 1) & 1;
            int j0 = jbase + (it - 1) * 2;
#pragma unroll
            for (int jq = 0; jq < 2; jq++) {
#pragma unroll
                for (int ii = 0; ii < 4; ii++) {
                    float ed = stf[jq * 1024 + ii * 256 + d];
#pragma unroll
                    for (int hh = 0; hh < 4; hh++)
                        g_r[ii * 4 + hh] =
                            fmaf(p_s[bprev][jq][ii * 8 + half * 4 + hh], ed, g_r[ii * 4 + hh]);
                }
                float o0 = bo, o1 = bo;
#pragma unroll
                for (int h = 0; h < 8; h++) {
                    float pj = ptf[jq * 2304 + d * 9 + h];
                    float2 a0 = a_s[bprev][jq][r0 * 8 + h];
                    float2 a1 = a_s[bprev][jq][r1 * 8 + h];
                    o0 = fmaf(a0.x, Pi0[h], fmaf(a0.y, pj, o0));
                    o1 = fmaf(a1.x, Pi1[h], fmaf(a1.y, pj, o1));
                }
                int j = j0 + jq;
                e_out[((size_t)(i0 + r0) * kN + j) * kD + d] = o0;
                e_out[((size_t)(i0 + r1) * kN + j) * kD + d] = o1;
            }
        }
    }

    // combine jq0/jq1 run_sum partials (seg0 holds jq0, seg8 holds jq1)
    run_sum += __shfl_xor_sync(0xffffffffu, run_sum, 8);

#pragma unroll
    for (int ii = 0; ii < 4; ii++)
#pragma unroll
        for (int hh = 0; hh < 4; hh++)
            g_part_g[(((size_t)ch * kN + i0 + ii) * 8 + half * 4 + hh) * 256 + d] =
                g_r[ii * 4 + hh];
    if (seg == 0)
        sum_part_g[((size_t)ch * kN + i0 + ii_s) * 8 + h_s] = run_sum;
}

// ---------------- K3: reduce + x_out, 2 nodes/CTA in parallel ----------------
// grid kN/2 = 192 CTAs, 512 threads: thread = (c = t&255, node = t>>8).
// Weight streams shared by both node-halves (same addresses -> L1 broadcast),
// halving L2 weight traffic vs 1 node/CTA.
__global__ __launch_bounds__(512) void k3_xout(
    const float* __restrict__ Wv_e, const float* __restrict__ bv_e,
    const float* __restrict__ WOx,  const float* __restrict__ bOx,
    float* __restrict__ x_out)
{
    __shared__ float gs[2][2048];
    __shared__ float xc[2][256];
    __shared__ float inv_s[16];
    int i0 = blockIdx.x * 2, t = threadIdx.x;
    int c = t & 255, nd = t >> 8;

    if (t < 16) {
        int n = t >> 3, h = t & 7;
        float s = sum_part_g[(size_t)(i0 + n) * 8 + h]
                + sum_part_g[((size_t)kN + i0 + n) * 8 + h]
                + sum_part_g[((size_t)2 * kN + i0 + n) * 8 + h];
        inv_s[t] = 1.f / s;
    }
    __syncthreads();
#pragma unroll
    for (int r = 0; r < 8; r++) {
        int idx = t + r * 512;           // 0..4095
        int n = idx >> 11, rest = idx & 2047, h = rest >> 8;
        float a = g_part_g[((size_t)(i0 + n) * 8 + h) * 256 + (rest & 255)]
                + g_part_g[(((size_t)kN + i0 + n) * 8 + h) * 256 + (rest & 255)]
                + g_part_g[(((size_t)2 * kN + i0 + n) * 8 + h) * 256 + (rest & 255)];
        gs[n][rest] = a * inv_s[n * 8 + h];
    }
    __syncthreads();

    // GEMV1: xc[nd][c] = gs[nd][h,:] . Wv_e[h,:,k] + bv_e[c]
    {
        int h = c >> 5, k = c & 31;
        const float* wv = Wv_e + h * 8192 + k;
        const float* gh = gs[nd] + h * 256;
        float a0 = 0.f, a1 = 0.f;
#pragma unroll 4
        for (int dd = 0; dd < kD; dd += 2) {
            a0 = fmaf(gh[dd],     wv[dd * 32],       a0);
            a1 = fmaf(gh[dd + 1], wv[(dd + 1) * 32], a1);
        }
        xc[nd][c] = a0 + a1 + bv_e[c];
    }
    __syncthreads();

    // GEMV2: x_out[i0+nd][c] = xc[nd] . WOx[:,c] + bOx[c]
    {
        const float* xv = xc[nd];
        float o0 = 0.f, o1 = 0.f;
#pragma unroll 4
        for (int cc = 0; cc < kD; cc += 2) {
            o0 = fmaf(xv[cc],     WOx[cc * kD + c],       o0);
            o1 = fmaf(xv[cc + 1], WOx[(cc + 1) * kD + c], o1);
        }
        x_out[(size_t)(i0 + nd) * kD + c] = o0 + o1 + bOx[c];
    }
}

// ---------------- launch -----------------------------------------------------
extern "C" void kernel_launch(void* const* d_in, const int* in_sizes, int n_in,
                              void* d_out, int out_size)
{
    (void)in_sizes; (void)n_in; (void)out_size;
    const float* x    = (const float*)d_in[0];
    const float* e    = (const float*)d_in[1];
    const float* Wq_x = (const float*)d_in[2];
    const float* bq_x = (const float*)d_in[3];
    const float* Wk_e = (const float*)d_in[4];
    const float* bk_e = (const float*)d_in[5];
    const float* Wv_e = (const float*)d_in[6];
    const float* bv_e = (const float*)d_in[7];
    const float* Wq_e = (const float*)d_in[8];
    const float* bq_e = (const float*)d_in[9];
    const float* Wk_x = (const float*)d_in[10];
    const float* bk_x = (const float*)d_in[11];
    const float* Wv_x = (const float*)d_in[12];
    const float* bv_x = (const float*)d_in[13];
    const float* WOx  = (const float*)d_in[14];
    const float* bOx  = (const float*)d_in[15];
    const float* WOe  = (const float*)d_in[16];
    const float* bOe  = (const float*)d_in[17];

    float* out   = (float*)d_out;
    float* x_out = out;                 // [384,256]
    float* e_out = out + kN * kD;       // [384,384,256]

    cudaFuncSetAttribute(k_fused, cudaFuncAttributeMaxDynamicSharedMemorySize, FUSED_SMEM);

    k1_proj<<<kN, 256>>>(x, Wq_x, bq_x, Wk_x, bk_x, Wv_x, bv_x, bk_e, bq_e);
    k1b_uwp<<<dim3(24, 8), 256>>>(Wk_e, Wq_e, WOe);
    k_fused<<<dim3(96, 3), 512, FUSED_SMEM>>>(e, bOe, e_out);
    k3_xout<<<kN / 2, 512>>>(Wv_e, bv_e, WOx, bOx, x_out);
}

// round 14
// speedup vs baseline: 1.2324x; 1.1658x over previous
#include <cuda_runtime.h>
#include <math.h>
#include <stdint.h>

static constexpr int kN  = 384;
static constexpr int kD  = 256;
static constexpr int kH  = 8;
static constexpr float kScale = 0.17677669529663687f;  // 1/sqrt(32)

// ---------------- scratch (__device__ globals; no allocation) ----------------
__device__ __align__(16) float qx_g[kN * kD];
__device__ __align__(16) float kx_g[kN * kD];
__device__ __align__(16) float vx_g[kN * kD];
__device__ __align__(16) float cen_g[kN * kH];          // qx . bk_e
__device__ __align__(16) float cne_g[kN * kH];          // kx . bq_e
__device__ __align__(16) float u_g[kN * kH * kD];       // [i][h][d]
__device__ __align__(16) float w_g[kN * kH * kD];       // [n][h][d]
__device__ __align__(16) float PT_g[kN * kD * 9];       // [n][d*9+h] stride-9 pad
__device__ __align__(16) float g_part_g[3 * kN * kH * kD];
__device__ __align__(16) float sum_part_g[3 * kN * kH];

__device__ __forceinline__ void cpa16(void* smem, const void* gmem)
{
    unsigned s = (unsigned)__cvta_generic_to_shared(smem);
    asm volatile("cp.async.ca.shared.global [%0], [%1], 16;\n" :: "r"(s), "l"(gmem));
}
#define CP_COMMIT() asm volatile("cp.async.commit_group;\n" ::: "memory")
#define CP_WAIT2()  asm volatile("cp.async.wait_group 2;\n" ::: "memory")

// ---------------- K1: i-blocked projections (weights read once per block) ----
// grid (24, 8), 256 threads. Block (ib,h): 16 nodes, one head.
// Thread (k = t&31, dg = t>>5): holds W[h, dg*32+dd, k] in wr[32] per pass.
__global__ __launch_bounds__(256) void k1_proj(
    const float* __restrict__ x,
    const float* __restrict__ Wq, const float* __restrict__ bq,
    const float* __restrict__ Wk, const float* __restrict__ bk,
    const float* __restrict__ Wv, const float* __restrict__ bv,
    const float* __restrict__ bk_e, const float* __restrict__ bq_e)
{
    __shared__ float xs[16 * 256];     // 16 nodes x 256 dims
    __shared__ float red[8 * 16 * 32]; // [dg][i][k]
    int ib = blockIdx.x, h = blockIdx.y;
    int t = threadIdx.x;
    int k = t & 31, dg = t >> 5;
    int lane = t & 31;

    // stage x rows (coalesced)
    for (int r = 0; r < 16; r++)
        xs[r * 256 + t] = x[(size_t)(ib * 16 + r) * kD + t];
    __syncthreads();

    const float* Wm[3]  = { Wq, Wk, Wv };
    const float* bm[3]  = { bq, bk, bv };
    float*       om[3];
    om[0] = qx_g; om[1] = kx_g; om[2] = vx_g;

    for (int m = 0; m < 3; m++) {
        // load this thread's weight slice: W[h, dg*32+dd, k]
        float wr[32];
        const float* wbase = Wm[m] + h * 8192 + (dg * 32) * 32 + k;
#pragma unroll
        for (int dd = 0; dd < 32; dd++) wr[dd] = wbase[dd * 32];

        // partials over this d-group for all 16 nodes
#pragma unroll 4
        for (int i = 0; i < 16; i++) {
            const float* xr = xs + i * 256 + dg * 32;
            float a0 = 0.f, a1 = 0.f;
#pragma unroll
            for (int dd = 0; dd < 32; dd += 2) {
                a0 = fmaf(wr[dd],     xr[dd],     a0);
                a1 = fmaf(wr[dd + 1], xr[dd + 1], a1);
            }
            red[dg * 512 + i * 32 + k] = a0 + a1;
        }
        __syncthreads();

        // reduce over the 8 d-groups; thread (ii2 = t>>5, k) handles i = rep*8+ii2
        {
            int ii2 = t >> 5;
            float bias = bm[m][h * 32 + k];
#pragma unroll
            for (int rep = 0; rep < 2; rep++) {
                int i = rep * 8 + ii2;
                float v = bias;
#pragma unroll
                for (int g = 0; g < 8; g++) v += red[g * 512 + i * 32 + k];
                om[m][(size_t)(ib * 16 + i) * kD + h * 32 + k] = v;

                if (m == 0) {           // cen = qx . bk_e
                    float ce = bk_e[h * 32 + k] * v;
#pragma unroll
                    for (int o = 16; o; o >>= 1)
                        ce += __shfl_xor_sync(0xffffffffu, ce, o);
                    if (lane == 0) cen_g[(ib * 16 + i) * kH + h] = ce;
                } else if (m == 1) {    // cne = kx . bq_e
                    float cn = bq_e[h * 32 + k] * v;
#pragma unroll
                    for (int o = 16; o; o >>= 1)
                        cn += __shfl_xor_sync(0xffffffffu, cn, o);
                    if (lane == 0) cne_g[(ib * 16 + i) * kH + h] = cn;
                }
            }
        }
        __syncthreads();
    }
}

// ---------------- K1b: u / w / PT tables -------------------------------------
__global__ __launch_bounds__(256) void k1b_uwp(
    const float* __restrict__ Wk_e,
    const float* __restrict__ Wq_e,
    const float* __restrict__ WOe)
{
    __shared__ float qs[16 * 32], ks[16 * 32], vs[16 * 32];
    int ib = blockIdx.x, h = blockIdx.y;
    int d = threadIdx.x;
    for (int idx = threadIdx.x; idx < 512; idx += 256) {
        int ii = idx >> 5, k = idx & 31;
        int g = (ib * 16 + ii) * kD + h * 32 + k;
        qs[idx] = qx_g[g]; ks[idx] = kx_g[g]; vs[idx] = vx_g[g];
    }
    __syncthreads();

    float wr[32];
#pragma unroll
    for (int k = 0; k < 32; k++) wr[k] = Wk_e[h * 8192 + d * 32 + k];
    for (int ii = 0; ii < 16; ii++) {
        float a = 0.f;
#pragma unroll
        for (int k = 0; k < 32; k++) a = fmaf(wr[k], qs[ii * 32 + k], a);
        u_g[((ib * 16 + ii) * kH + h) * kD + d] = a;
    }
#pragma unroll
    for (int k = 0; k < 32; k++) wr[k] = Wq_e[h * 8192 + d * 32 + k];
    for (int ii = 0; ii < 16; ii++) {
        float a = 0.f;
#pragma unroll
        for (int k = 0; k < 32; k++) a = fmaf(wr[k], ks[ii * 32 + k], a);
        w_g[((ib * 16 + ii) * kH + h) * kD + d] = a;
    }
#pragma unroll
    for (int k = 0; k < 32; k++) wr[k] = WOe[(h * 32 + k) * kD + d];
    for (int ii = 0; ii < 16; ii++) {
        float a = 0.f;
#pragma unroll
        for (int k = 0; k < 32; k++) a = fmaf(wr[k], vs[ii * 32 + k], a);
        PT_g[(size_t)(ib * 16 + ii) * 2304 + d * 9 + h] = a;
    }
}

// ---------------- K_fused: pipelined scores/softmax/g/e_out ------------------
// EXACT R6 configuration (best measured: 364.7us).
// 4 i-rows, 2 j per slot, 4-slot cp.async ring, 1 barrier/iter, 512 thr.
// Slot (float4): E 512 | W 1024 | PT 1152 | cne 4  = 2692 f4 = 43072 B.
static constexpr int STG_F4 = 2692;
static constexpr int FUSED_SMEM = 4 * STG_F4 * 16;   // 172288 B

__device__ __forceinline__ void kf_prefetch(float4* st, const float* e, int i0, int j0)
{
    int t = threadIdx.x;
#pragma unroll
    for (int k = 0; k < 6; k++) {
        int idx = t + k * 512;
        if (idx >= STG_F4) break;
        if (idx < 512) {
            int jq = idx >> 8, r = idx & 255;
            int ii = r >> 6, c = r & 63;
            cpa16(st + idx,
                  (const float4*)(e) + ((size_t)(i0 + ii) * kN + (j0 + jq)) * 64 + c);
        } else if (idx < 1536) {
            int r = idx - 512;
            int jq = r >> 9, q = r & 511;
            cpa16(st + idx, (const float4*)w_g + (size_t)(j0 + jq) * 512 + q);
        } else if (idx < 2688) {
            int r = idx - 1536;
            int jq = (r >= 576) ? 1 : 0;
            int q  = r - jq * 576;
            cpa16(st + idx, (const float4*)PT_g + (size_t)(j0 + jq) * 576 + q);
        } else {
            cpa16(st + idx, (const float4*)cne_g + (size_t)j0 * 2 + (idx - 2688));
        }
    }
}

__global__ __launch_bounds__(512, 1) void k_fused(
    const float* __restrict__ e, const float* __restrict__ bOe,
    float* __restrict__ e_out)
{
    extern __shared__ float4 smem4[];
    __shared__ float  p_s[2][2][32];
    __shared__ float2 a_s[2][2][32];
    __shared__ float  cen_s[32], cnei_s[32];

    int t = threadIdx.x;
    int i0 = blockIdx.x * 4;
    int ch = blockIdx.y;
    int jbase = ch * 128;

    int p = t >> 4, seg = t & 15;       // score: 32 (ii,h) pairs x 16 segs
    int ii_s = p >> 3, h_s = p & 7;
    int d = t & 255, half = t >> 8;     // g/out mapping
    int r0 = half * 2, r1 = half * 2 + 1;

    if (t < 32) { cen_s[t] = cen_g[i0 * 8 + t]; cnei_s[t] = cne_g[i0 * 8 + t]; }

    float4 u_r[4], wi_r[4];
    {
        const float4* ub = (const float4*)u_g + ((size_t)(i0 + ii_s) * 8 + h_s) * 64;
        const float4* wb = (const float4*)w_g + ((size_t)(i0 + ii_s) * 8 + h_s) * 64;
#pragma unroll
        for (int k = 0; k < 4; k++) { u_r[k] = ub[seg + 16 * k]; wi_r[k] = wb[seg + 16 * k]; }
    }
    float Pi0[8], Pi1[8];
#pragma unroll
    for (int h = 0; h < 8; h++) {
        Pi0[h] = PT_g[(size_t)(i0 + r0) * 2304 + d * 9 + h];
        Pi1[h] = PT_g[(size_t)(i0 + r1) * 2304 + d * 9 + h];
    }
    float bo = bOe[d];
    float g_r[16];
#pragma unroll
    for (int q = 0; q < 16; q++) g_r[q] = 0.f;
    float run_sum = 0.f;

    kf_prefetch(smem4,          e, i0, jbase);     CP_COMMIT();
    kf_prefetch(smem4 + STG_F4, e, i0, jbase + 2); CP_COMMIT();

    for (int it = 0; it <= 64; it++) {
        __syncthreads();   // separates score[it-1] p/a writes from out[it] reads,
                           // and all reads of slot (it+2)&3 from its overwrite
        if (it + 2 < 64)
            kf_prefetch(smem4 + (size_t)((it + 2) & 3) * STG_F4, e, i0, jbase + (it + 2) * 2);
        CP_COMMIT();
        CP_WAIT2();        // slot it&3 data ready

        if (it < 64) {
            // ---- score phase on slot it ----
            const float4* st4 = smem4 + (size_t)(it & 3) * STG_F4;
            int buf = it & 1;
            float acc[6];
#pragma unroll
            for (int q = 0; q < 6; q++) acc[q] = 0.f;
#pragma unroll
            for (int k = 0; k < 4; k++) {
                float4 uu = u_r[k], wi = wi_r[k];
#pragma unroll
                for (int jq = 0; jq < 2; jq++) {
                    float4 ev = st4[jq * 256 + ii_s * 64 + seg + 16 * k];
                    float4 wj = st4[512 + jq * 512 + h_s * 64 + seg + 16 * k];
                    float* a = acc + jq * 3;
                    a[0] = fmaf(ev.x, uu.x, a[0]); a[0] = fmaf(ev.y, uu.y, a[0]);
                    a[0] = fmaf(ev.z, uu.z, a[0]); a[0] = fmaf(ev.w, uu.w, a[0]);
                    a[1] = fmaf(ev.x, wi.x, a[1]); a[1] = fmaf(ev.y, wi.y, a[1]);
                    a[1] = fmaf(ev.z, wi.z, a[1]); a[1] = fmaf(ev.w, wi.w, a[1]);
                    a[2] = fmaf(ev.x, wj.x, a[2]); a[2] = fmaf(ev.y, wj.y, a[2]);
                    a[2] = fmaf(ev.z, wj.z, a[2]); a[2] = fmaf(ev.w, wj.w, a[2]);
                }
            }
#pragma unroll
            for (int o = 1; o < 16; o <<= 1)
#pragma unroll
                for (int q = 0; q < 6; q++)
                    acc[q] += __shfl_xor_sync(0xffffffffu, acc[q], o);

            if ((seg & 7) == 0) {          // seg 0 -> jq 0, seg 8 -> jq 1
                int jq = seg >> 3;
                float pe = __expf((acc[jq * 3] + cen_s[p]) * kScale);
                run_sum += pe;
                p_s[buf][jq][p] = pe;
                float si = (acc[jq * 3 + 1] + cnei_s[p]) * kScale;
                float sj = (acc[jq * 3 + 2] + ((const float*)st4)[10752 + jq * 8 + h_s]) * kScale;
                float ei = __expf(si), ej = __expf(sj);
                float inv = 1.f / (ei + ej);
                a_s[buf][jq][p] = make_float2(ei * inv, ej * inv);
            }
        }

        if (it > 0) {
            // ---- g + out phase on slot it-1 ----
            const float* stf = (const float*)(smem4 + (size_t)((it - 1) & 3) * STG_F4);
            const float* ptf = stf + 6144;
            int bprev = (it - 1) & 1;
            int j0 = jbase + (it - 1) * 2;
#pragma unroll
            for (int jq = 0; jq < 2; jq++) {
#pragma unroll
                for (int ii = 0; ii < 4; ii++) {
                    float ed = stf[jq * 1024 + ii * 256 + d];
#pragma unroll
                    for (int hh = 0; hh < 4; hh++)
                        g_r[ii * 4 + hh] =
                            fmaf(p_s[bprev][jq][ii * 8 + half * 4 + hh], ed, g_r[ii * 4 + hh]);
                }
                float o0 = bo, o1 = bo;
#pragma unroll
                for (int h = 0; h < 8; h++) {
                    float pj = ptf[jq * 2304 + d * 9 + h];
                    float2 a0 = a_s[bprev][jq][r0 * 8 + h];
                    float2 a1 = a_s[bprev][jq][r1 * 8 + h];
                    o0 = fmaf(a0.x, Pi0[h], fmaf(a0.y, pj, o0));
                    o1 = fmaf(a1.x, Pi1[h], fmaf(a1.y, pj, o1));
                }
                int j = j0 + jq;
                e_out[((size_t)(i0 + r0) * kN + j) * kD + d] = o0;
                e_out[((size_t)(i0 + r1) * kN + j) * kD + d] = o1;
            }
        }
    }

    // combine jq0/jq1 run_sum partials (seg0 holds jq0, seg8 holds jq1)
    run_sum += __shfl_xor_sync(0xffffffffu, run_sum, 8);

#pragma unroll
    for (int ii = 0; ii < 4; ii++)
#pragma unroll
        for (int hh = 0; hh < 4; hh++)
            g_part_g[(((size_t)ch * kN + i0 + ii) * 8 + half * 4 + hh) * 256 + d] =
                g_r[ii * 4 + hh];
    if (seg == 0)
        sum_part_g[((size_t)ch * kN + i0 + ii_s) * 8 + h_s] = run_sum;
}

// ---------------- K3: reduce + x_out, split-d (R9 version, 21.7us) -----------
__global__ __launch_bounds__(512) void k3_xout(
    const float* __restrict__ Wv_e, const float* __restrict__ bv_e,
    const float* __restrict__ WOx,  const float* __restrict__ bOx,
    float* __restrict__ x_out)
{
    __shared__ float gs[2048];
    __shared__ float xc[256];
    __shared__ float part[512];
    __shared__ float inv_s[8];
    int i = blockIdx.x, t = threadIdx.x;
    int c = t & 255, pr = t >> 8;

    if (t < 8) {
        float s = sum_part_g[(size_t)i * 8 + t]
                + sum_part_g[((size_t)kN + i) * 8 + t]
                + sum_part_g[((size_t)2 * kN + i) * 8 + t];
        inv_s[t] = 1.f / s;
    }
    __syncthreads();
#pragma unroll
    for (int r = 0; r < 4; r++) {
        int idx = t + r * 512;
        int h = idx >> 8;
        float a = g_part_g[((size_t)i * 8 + h) * 256 + (idx & 255)]
                + g_part_g[(((size_t)kN + i) * 8 + h) * 256 + (idx & 255)]
                + g_part_g[(((size_t)2 * kN + i) * 8 + h) * 256 + (idx & 255)];
        gs[idx] = a * inv_s[h];
    }
    __syncthreads();

    // GEMV1: xc[c] = gs[h,:] . Wv_e[h,:,k], split over d halves
    {
        int h = c >> 5, k = c & 31;
        const float* wv = Wv_e + h * 8192 + k;
        const float* gh = gs + h * 256;
        float a0 = 0.f, a1 = 0.f;
        int dbeg = pr * 128;
#pragma unroll 4
        for (int dd = dbeg; dd < dbeg + 128; dd += 2) {
            a0 = fmaf(gh[dd],     wv[dd * 32],       a0);
            a1 = fmaf(gh[dd + 1], wv[(dd + 1) * 32], a1);
        }
        part[t] = a0 + a1;
    }
    __syncthreads();
    if (t < 256) xc[t] = part[t] + part[t + 256] + bv_e[t];
    __syncthreads();

    // GEMV2: x_out[c] = xc . WOx[:,c], split over cc halves
    {
        float o0 = 0.f, o1 = 0.f;
        int cbeg = pr * 128;
#pragma unroll 4
        for (int cc = cbeg; cc < cbeg + 128; cc += 2) {
            o0 = fmaf(xc[cc],     WOx[cc * kD + c],       o0);
            o1 = fmaf(xc[cc + 1], WOx[(cc + 1) * kD + c], o1);
        }
        part[t] = o0 + o1;
    }
    __syncthreads();
    if (t < 256) x_out[(size_t)i * kD + t] = part[t] + part[t + 256] + bOx[t];
}

// ---------------- launch -----------------------------------------------------
extern "C" void kernel_launch(void* const* d_in, const int* in_sizes, int n_in,
                              void* d_out, int out_size)
{
    (void)in_sizes; (void)n_in; (void)out_size;
    const float* x    = (const float*)d_in[0];
    const float* e    = (const float*)d_in[1];
    const float* Wq_x = (const float*)d_in[2];
    const float* bq_x = (const float*)d_in[3];
    const float* Wk_e = (const float*)d_in[4];
    const float* bk_e = (const float*)d_in[5];
    const float* Wv_e = (const float*)d_in[6];
    const float* bv_e = (const float*)d_in[7];
    const float* Wq_e = (const float*)d_in[8];
    const float* bq_e = (const float*)d_in[9];
    const float* Wk_x = (const float*)d_in[10];
    const float* bk_x = (const float*)d_in[11];
    const float* Wv_x = (const float*)d_in[12];
    const float* bv_x = (const float*)d_in[13];
    const float* WOx  = (const float*)d_in[14];
    const float* bOx  = (const float*)d_in[15];
    const float* WOe  = (const float*)d_in[16];
    const float* bOe  = (const float*)d_in[17];

    float* out   = (float*)d_out;
    float* x_out = out;                 // [384,256]
    float* e_out = out + kN * kD;       // [384,384,256]

    cudaFuncSetAttribute(k_fused, cudaFuncAttributeMaxDynamicSharedMemorySize, FUSED_SMEM);

    k1_proj<<<dim3(24, 8), 256>>>(x, Wq_x, bq_x, Wk_x, bk_x, Wv_x, bv_x, bk_e, bq_e);
    k1b_uwp<<<dim3(24, 8), 256>>>(Wk_e, Wq_e, WOe);
    k_fused<<<dim3(96, 3), 512, FUSED_SMEM>>>(e, bOe, e_out);
    k3_xout<<<kN, 512>>>(Wv_e, bv_e, WOx, bOx, x_out);
}

// round 16
// speedup vs baseline: 1.2325x; 1.0001x over previous
#include <cuda_runtime.h>
#include <math.h>
#include <stdint.h>

static constexpr int kN  = 384;
static constexpr int kD  = 256;
static constexpr int kH  = 8;
static constexpr float kScale = 0.17677669529663687f;  // 1/sqrt(32)

// ---------------- scratch (__device__ globals; no allocation) ----------------
__device__ __align__(16) float cen_g[kN * kH];          // qx . bk_e
__device__ __align__(16) float cne_g[kN * kH];          // kx . bq_e
__device__ __align__(16) float u_g[kN * kH * kD];       // [i][h][d]
__device__ __align__(16) float w_g[kN * kH * kD];       // [n][h][d]
__device__ __align__(16) float PT_g[kN * kD * 9];       // [n][d*9+h] stride-9 pad
__device__ __align__(16) float g_part_g[3 * kN * kH * kD];
__device__ __align__(16) float sum_part_g[3 * kN * kH];

__device__ __forceinline__ void cpa16(void* smem, const void* gmem)
{
    unsigned s = (unsigned)__cvta_generic_to_shared(smem);
    asm volatile("cp.async.ca.shared.global [%0], [%1], 16;\n" :: "r"(s), "l"(gmem));
}
#define CP_COMMIT() asm volatile("cp.async.commit_group;\n" ::: "memory")
#define CP_WAIT2()  asm volatile("cp.async.wait_group 2;\n" ::: "memory")

// ---------------- K1: fused projections + u/w/PT tables ----------------------
// grid (24, 8), 256 threads. Block (ib,h): 16 nodes, one head.
// Pass m: project x through Wm (weights in regs), reduce to pr_s (smem),
// then transform pr_s through the m-th edge-side table into u/w/PT.
__global__ __launch_bounds__(256) void k1_all(
    const float* __restrict__ x,
    const float* __restrict__ Wq, const float* __restrict__ bq,
    const float* __restrict__ Wk, const float* __restrict__ bk,
    const float* __restrict__ Wv, const float* __restrict__ bv,
    const float* __restrict__ bk_e, const float* __restrict__ bq_e,
    const float* __restrict__ Wk_e, const float* __restrict__ Wq_e,
    const float* __restrict__ WOe)
{
    __shared__ float xs[16 * 256];     // 16 nodes x 256 dims
    __shared__ float red[8 * 16 * 32]; // [dg][i][k]
    __shared__ float pr_s[16 * 32];    // projected q/k/v for current pass
    int ib = blockIdx.x, h = blockIdx.y;
    int t = threadIdx.x;
    int k = t & 31, dg = t >> 5;
    int lane = t & 31;
    int d = t;                          // second-stage mapping: thread = d

    for (int r = 0; r < 16; r++)
        xs[r * 256 + t] = x[(size_t)(ib * 16 + r) * kD + t];
    __syncthreads();

    const float* Wm[3] = { Wq, Wk, Wv };
    const float* bm[3] = { bq, bk, bv };

    for (int m = 0; m < 3; m++) {
        // ---- stage 1: projection, weights in registers ----
        float wr[32];
        const float* wbase = Wm[m] + h * 8192 + (dg * 32) * 32 + k;
#pragma unroll
        for (int dd = 0; dd < 32; dd++) wr[dd] = wbase[dd * 32];

#pragma unroll 4
        for (int i = 0; i < 16; i++) {
            const float* xr = xs + i * 256 + dg * 32;
            float a0 = 0.f, a1 = 0.f;
#pragma unroll
            for (int dd = 0; dd < 32; dd += 2) {
                a0 = fmaf(wr[dd],     xr[dd],     a0);
                a1 = fmaf(wr[dd + 1], xr[dd + 1], a1);
            }
            red[dg * 512 + i * 32 + k] = a0 + a1;
        }
        __syncthreads();

        // ---- reduce 8 d-groups -> pr_s; cen/cne constants ----
        {
            int ii2 = t >> 5;
            float bias = bm[m][h * 32 + k];
#pragma unroll
            for (int rep = 0; rep < 2; rep++) {
                int i = rep * 8 + ii2;
                float v = bias;
#pragma unroll
                for (int g = 0; g < 8; g++) v += red[g * 512 + i * 32 + k];
                pr_s[i * 32 + k] = v;

                if (m == 0) {           // cen = qx . bk_e
                    float ce = bk_e[h * 32 + k] * v;
#pragma unroll
                    for (int o = 16; o; o >>= 1)
                        ce += __shfl_xor_sync(0xffffffffu, ce, o);
                    if (lane == 0) cen_g[(ib * 16 + i) * kH + h] = ce;
                } else if (m == 1) {    // cne = kx . bq_e
                    float cn = bq_e[h * 32 + k] * v;
#pragma unroll
                    for (int o = 16; o; o >>= 1)
                        cn += __shfl_xor_sync(0xffffffffu, cn, o);
                    if (lane == 0) cne_g[(ib * 16 + i) * kH + h] = cn;
                }
            }
        }
        __syncthreads();

        // ---- stage 2: table transform from pr_s (thread = d) ----
        float wr2[32];
        if (m == 0) {
#pragma unroll
            for (int kk = 0; kk < 32; kk++) wr2[kk] = Wk_e[h * 8192 + d * 32 + kk];
        } else if (m == 1) {
#pragma unroll
            for (int kk = 0; kk < 32; kk++) wr2[kk] = Wq_e[h * 8192 + d * 32 + kk];
        } else {
#pragma unroll
            for (int kk = 0; kk < 32; kk++) wr2[kk] = WOe[(h * 32 + kk) * kD + d];
        }
        for (int ii = 0; ii < 16; ii++) {
            float a = 0.f;
#pragma unroll
            for (int kk = 0; kk < 32; kk++) a = fmaf(wr2[kk], pr_s[ii * 32 + kk], a);
            if (m == 0)
                u_g[((size_t)(ib * 16 + ii) * kH + h) * kD + d] = a;
            else if (m == 1)
                w_g[((size_t)(ib * 16 + ii) * kH + h) * kD + d] = a;
            else
                PT_g[(size_t)(ib * 16 + ii) * 2304 + d * 9 + h] = a;
        }
        __syncthreads();   // pr_s / red reused next pass
    }
}

// ---------------- K_fused: pipelined scores/softmax/g/e_out ------------------
// EXACT R13 configuration (best measured: 327.7us).
// 4 i-rows, 2 j per slot, 4-slot cp.async ring, 1 barrier/iter, 512 thr.
// Slot (float4): E 512 | W 1024 | PT 1152 | cne 4  = 2692 f4 = 43072 B.
static constexpr int STG_F4 = 2692;
static constexpr int FUSED_SMEM = 4 * STG_F4 * 16;   // 172288 B

__device__ __forceinline__ void kf_prefetch(float4* st, const float* e, int i0, int j0)
{
    int t = threadIdx.x;
#pragma unroll
    for (int k = 0; k < 6; k++) {
        int idx = t + k * 512;
        if (idx >= STG_F4) break;
        if (idx < 512) {
            int jq = idx >> 8, r = idx & 255;
            int ii = r >> 6, c = r & 63;
            cpa16(st + idx,
                  (const float4*)(e) + ((size_t)(i0 + ii) * kN + (j0 + jq)) * 64 + c);
        } else if (idx < 1536) {
            int r = idx - 512;
            int jq = r >> 9, q = r & 511;
            cpa16(st + idx, (const float4*)w_g + (size_t)(j0 + jq) * 512 + q);
        } else if (idx < 2688) {
            int r = idx - 1536;
            int jq = (r >= 576) ? 1 : 0;
            int q  = r - jq * 576;
            cpa16(st + idx, (const float4*)PT_g + (size_t)(j0 + jq) * 576 + q);
        } else {
            cpa16(st + idx, (const float4*)cne_g + (size_t)j0 * 2 + (idx - 2688));
        }
    }
}

__global__ __launch_bounds__(512, 1) void k_fused(
    const float* __restrict__ e, const float* __restrict__ bOe,
    float* __restrict__ e_out)
{
    extern __shared__ float4 smem4[];
    __shared__ float  p_s[2][2][32];
    __shared__ float2 a_s[2][2][32];
    __shared__ float  cen_s[32], cnei_s[32];

    int t = threadIdx.x;
    int i0 = blockIdx.x * 4;
    int ch = blockIdx.y;
    int jbase = ch * 128;

    int p = t >> 4, seg = t & 15;       // score: 32 (ii,h) pairs x 16 segs
    int ii_s = p >> 3, h_s = p & 7;
    int d = t & 255, half = t >> 8;     // g/out mapping
    int r0 = half * 2, r1 = half * 2 + 1;

    if (t < 32) { cen_s[t] = cen_g[i0 * 8 + t]; cnei_s[t] = cne_g[i0 * 8 + t]; }

    float4 u_r[4], wi_r[4];
    {
        const float4* ub = (const float4*)u_g + ((size_t)(i0 + ii_s) * 8 + h_s) * 64;
        const float4* wb = (const float4*)w_g + ((size_t)(i0 + ii_s) * 8 + h_s) * 64;
#pragma unroll
        for (int k = 0; k < 4; k++) { u_r[k] = ub[seg + 16 * k]; wi_r[k] = wb[seg + 16 * k]; }
    }
    float Pi0[8], Pi1[8];
#pragma unroll
    for (int h = 0; h < 8; h++) {
        Pi0[h] = PT_g[(size_t)(i0 + r0) * 2304 + d * 9 + h];
        Pi1[h] = PT_g[(size_t)(i0 + r1) * 2304 + d * 9 + h];
    }
    float bo = bOe[d];
    float g_r[16];
#pragma unroll
    for (int q = 0; q < 16; q++) g_r[q] = 0.f;
    float run_sum = 0.f;

    kf_prefetch(smem4,          e, i0, jbase);     CP_COMMIT();
    kf_prefetch(smem4 + STG_F4, e, i0, jbase + 2); CP_COMMIT();

    for (int it = 0; it <= 64; it++) {
        __syncthreads();   // separates score[it-1] p/a writes from out[it] reads,
                           // and all reads of slot (it+2)&3 from its overwrite
        if (it + 2 < 64)
            kf_prefetch(smem4 + (size_t)((it + 2) & 3) * STG_F4, e, i0, jbase + (it + 2) * 2);
        CP_COMMIT();
        CP_WAIT2();        // slot it&3 data ready

        if (it < 64) {
            // ---- score phase on slot it ----
            const float4* st4 = smem4 + (size_t)(it & 3) * STG_F4;
            int buf = it & 1;
            float acc[6];
#pragma unroll
            for (int q = 0; q < 6; q++) acc[q] = 0.f;
#pragma unroll
            for (int k = 0; k < 4; k++) {
                float4 uu = u_r[k], wi = wi_r[k];
#pragma unroll
                for (int jq = 0; jq < 2; jq++) {
                    float4 ev = st4[jq * 256 + ii_s * 64 + seg + 16 * k];
                    float4 wj = st4[512 + jq * 512 + h_s * 64 + seg + 16 * k];
                    float* a = acc + jq * 3;
                    a[0] = fmaf(ev.x, uu.x, a[0]); a[0] = fmaf(ev.y, uu.y, a[0]);
                    a[0] = fmaf(ev.z, uu.z, a[0]); a[0] = fmaf(ev.w, uu.w, a[0]);
                    a[1] = fmaf(ev.x, wi.x, a[1]); a[1] = fmaf(ev.y, wi.y, a[1]);
                    a[1] = fmaf(ev.z, wi.z, a[1]); a[1] = fmaf(ev.w, wi.w, a[1]);
                    a[2] = fmaf(ev.x, wj.x, a[2]); a[2] = fmaf(ev.y, wj.y, a[2]);
                    a[2] = fmaf(ev.z, wj.z, a[2]); a[2] = fmaf(ev.w, wj.w, a[2]);
                }
            }
#pragma unroll
            for (int o = 1; o < 16; o <<= 1)
#pragma unroll
                for (int q = 0; q < 6; q++)
                    acc[q] += __shfl_xor_sync(0xffffffffu, acc[q], o);

            if ((seg & 7) == 0) {          // seg 0 -> jq 0, seg 8 -> jq 1
                int jq = seg >> 3;
                float pe = __expf((acc[jq * 3] + cen_s[p]) * kScale);
                run_sum += pe;
                p_s[buf][jq][p] = pe;
                float si = (acc[jq * 3 + 1] + cnei_s[p]) * kScale;
                float sj = (acc[jq * 3 + 2] + ((const float*)st4)[10752 + jq * 8 + h_s]) * kScale;
                float ei = __expf(si), ej = __expf(sj);
                float inv = 1.f / (ei + ej);
                a_s[buf][jq][p] = make_float2(ei * inv, ej * inv);
            }
        }

        if (it > 0) {
            // ---- g + out phase on slot it-1 ----
            const float* stf = (const float*)(smem4 + (size_t)((it - 1) & 3) * STG_F4);
            const float* ptf = stf + 6144;
            int bprev = (it - 1) & 1;
            int j0 = jbase + (it - 1) * 2;
#pragma unroll
            for (int jq = 0; jq < 2; jq++) {
#pragma unroll
                for (int ii = 0; ii < 4; ii++) {
                    float ed = stf[jq * 1024 + ii * 256 + d];
#pragma unroll
                    for (int hh = 0; hh < 4; hh++)
                        g_r[ii * 4 + hh] =
                            fmaf(p_s[bprev][jq][ii * 8 + half * 4 + hh], ed, g_r[ii * 4 + hh]);
                }
                float o0 = bo, o1 = bo;
#pragma unroll
                for (int h = 0; h < 8; h++) {
                    float pj = ptf[jq * 2304 + d * 9 + h];
                    float2 a0 = a_s[bprev][jq][r0 * 8 + h];
                    float2 a1 = a_s[bprev][jq][r1 * 8 + h];
                    o0 = fmaf(a0.x, Pi0[h], fmaf(a0.y, pj, o0));
                    o1 = fmaf(a1.x, Pi1[h], fmaf(a1.y, pj, o1));
                }
                int j = j0 + jq;
                e_out[((size_t)(i0 + r0) * kN + j) * kD + d] = o0;
                e_out[((size_t)(i0 + r1) * kN + j) * kD + d] = o1;
            }
        }
    }

    // combine jq0/jq1 run_sum partials (seg0 holds jq0, seg8 holds jq1)
    run_sum += __shfl_xor_sync(0xffffffffu, run_sum, 8);

#pragma unroll
    for (int ii = 0; ii < 4; ii++)
#pragma unroll
        for (int hh = 0; hh < 4; hh++)
            g_part_g[(((size_t)ch * kN + i0 + ii) * 8 + half * 4 + hh) * 256 + d] =
                g_r[ii * 4 + hh];
    if (seg == 0)
        sum_part_g[((size_t)ch * kN + i0 + ii_s) * 8 + h_s] = run_sum;
}

// ---------------- K3: reduce + x_out, split-d (R13 version) ------------------
__global__ __launch_bounds__(512) void k3_xout(
    const float* __restrict__ Wv_e, const float* __restrict__ bv_e,
    const float* __restrict__ WOx,  const float* __restrict__ bOx,
    float* __restrict__ x_out)
{
    __shared__ float gs[2048];
    __shared__ float xc[256];
    __shared__ float part[512];
    __shared__ float inv_s[8];
    int i = blockIdx.x, t = threadIdx.x;
    int c = t & 255, pr = t >> 8;

    if (t < 8) {
        float s = sum_part_g[(size_t)i * 8 + t]
                + sum_part_g[((size_t)kN + i) * 8 + t]
                + sum_part_g[((size_t)2 * kN + i) * 8 + t];
        inv_s[t] = 1.f / s;
    }
    __syncthreads();
#pragma unroll
    for (int r = 0; r < 4; r++) {
        int idx = t + r * 512;
        int h = idx >> 8;
        float a = g_part_g[((size_t)i * 8 + h) * 256 + (idx & 255)]
                + g_part_g[(((size_t)kN + i) * 8 + h) * 256 + (idx & 255)]
                + g_part_g[(((size_t)2 * kN + i) * 8 + h) * 256 + (idx & 255)];
        gs[idx] = a * inv_s[h];
    }
    __syncthreads();

    // GEMV1: xc[c] = gs[h,:] . Wv_e[h,:,k], split over d halves
    {
        int h = c >> 5, k = c & 31;
        const float* wv = Wv_e + h * 8192 + k;
        const float* gh = gs + h * 256;
        float a0 = 0.f, a1 = 0.f;
        int dbeg = pr * 128;
#pragma unroll 4
        for (int dd = dbeg; dd < dbeg + 128; dd += 2) {
            a0 = fmaf(gh[dd],     wv[dd * 32],       a0);
            a1 = fmaf(gh[dd + 1], wv[(dd + 1) * 32], a1);
        }
        part[t] = a0 + a1;
    }
    __syncthreads();
    if (t < 256) xc[t] = part[t] + part[t + 256] + bv_e[t];
    __syncthreads();

    // GEMV2: x_out[c] = xc . WOx[:,c], split over cc halves
    {
        float o0 = 0.f, o1 = 0.f;
        int cbeg = pr * 128;
#pragma unroll 4
        for (int cc = cbeg; cc < cbeg + 128; cc += 2) {
            o0 = fmaf(xc[cc],     WOx[cc * kD + c],       o0);
            o1 = fmaf(xc[cc + 1], WOx[(cc + 1) * kD + c], o1);
        }
        part[t] = o0 + o1;
    }
    __syncthreads();
    if (t < 256) x_out[(size_t)i * kD + t] = part[t] + part[t + 256] + bOx[t];
}

// ---------------- launch -----------------------------------------------------
extern "C" void kernel_launch(void* const* d_in, const int* in_sizes, int n_in,
                              void* d_out, int out_size)
{
    (void)in_sizes; (void)n_in; (void)out_size;
    const float* x    = (const float*)d_in[0];
    const float* e    = (const float*)d_in[1];
    const float* Wq_x = (const float*)d_in[2];
    const float* bq_x = (const float*)d_in[3];
    const float* Wk_e = (const float*)d_in[4];
    const float* bk_e = (const float*)d_in[5];
    const float* Wv_e = (const float*)d_in[6];
    const float* bv_e = (const float*)d_in[7];
    const float* Wq_e = (const float*)d_in[8];
    const float* bq_e = (const float*)d_in[9];
    const float* Wk_x = (const float*)d_in[10];
    const float* bk_x = (const float*)d_in[11];
    const float* Wv_x = (const float*)d_in[12];
    const float* bv_x = (const float*)d_in[13];
    const float* WOx  = (const float*)d_in[14];
    const float* bOx  = (const float*)d_in[15];
    const float* WOe  = (const float*)d_in[16];
    const float* bOe  = (const float*)d_in[17];

    float* out   = (float*)d_out;
    float* x_out = out;                 // [384,256]
    float* e_out = out + kN * kD;       // [384,384,256]

    cudaFuncSetAttribute(k_fused, cudaFuncAttributeMaxDynamicSharedMemorySize, FUSED_SMEM);

    k1_all<<<dim3(24, 8), 256>>>(x, Wq_x, bq_x, Wk_x, bk_x, Wv_x, bv_x,
                                 bk_e, bq_e, Wk_e, Wq_e, WOe);
    k_fused<<<dim3(96, 3), 512, FUSED_SMEM>>>(e, bOe, e_out);
    k3_xout<<<kN, 512>>>(Wv_e, bv_e, WOx, bOx, x_out);
}